// round 12
// baseline (speedup 1.0000x reference)
#include <cuda_runtime.h>
#include <cuda_bf16.h>
#include <cstdint>

#define N_NODES 100000
#define F 128
#define MAXE 1600000
#define SCAN_BS 1024
#define SCAN_NB ((N_NODES + SCAN_BS - 1) / SCAN_BS)   // 98

#define TILE_M 32
#define NT2 (N_NODES / TILE_M)                         // 3125 exact (all rows valid)
#define LDAB 528                                       // 512B data + 16B pad
#define ABUF_LO 16896
#define ABUF_SZ 33792
#define OFF_BHI (2 * ABUF_SZ)                          // 67584
#define OFF_BLO (OFF_BHI + 128 * LDAB)                 // 135168
#define SMEM_T  (OFF_BLO + 128 * LDAB)                 // 202752

// Scratch (allocation-free rule: __device__ globals)
__device__ int   g_cnt[N_NODES];
__device__ int   g_cur[N_NODES];
__device__ int   g_off[N_NODES];
__device__ int   g_bsum[SCAN_NB + 1];
__device__ int   g_csr[MAXE];
// bf16 packed x: one uint2 = 4 bf16 (8B); 128 feats = 32 uint2 = 256B/row
__device__ uint2 g_xhi[N_NODES * 32];
__device__ uint2 g_xlo[N_NODES * 32];

// ---- bf16 rn split: hi = rn(v) (unbiased), lo = rn(v - float(hi)) ----
__device__ __forceinline__ uint32_t cvt2(float f0, float f1) {
    uint32_t d;
    asm("cvt.rn.bf16x2.f32 %0, %1, %2;" : "=r"(d) : "f"(f1), "f"(f0));
    return d;
}
__device__ __forceinline__ float4 bf4_to_f4(uint2 p) {
    float2 a = __bfloat1622float2(*(const __nv_bfloat162*)&p.x);
    float2 b = __bfloat1622float2(*(const __nv_bfloat162*)&p.y);
    return make_float4(a.x, a.y, b.x, b.y);
}
__device__ __forceinline__ void split4(float4 v, uint2& hi, uint2& lo) {
    hi.x = cvt2(v.x, v.y);
    hi.y = cvt2(v.z, v.w);
    float4 h = bf4_to_f4(hi);
    lo.x = cvt2(v.x - h.x, v.y - h.y);
    lo.y = cvt2(v.z - h.z, v.w - h.w);
}

#define MMA16816(c, a0, a1, a2, a3, b0, b1) \
    asm volatile("mma.sync.aligned.m16n8k16.row.col.f32.bf16.bf16.f32 " \
                 "{%0,%1,%2,%3}, {%4,%5,%6,%7}, {%8,%9}, {%0,%1,%2,%3};" \
                 : "+f"((c)[0]), "+f"((c)[1]), "+f"((c)[2]), "+f"((c)[3]) \
                 : "r"(a0), "r"(a1), "r"(a2), "r"(a3), "r"(b0), "r"(b1))
#define LDSM4(r0, r1, r2, r3, addr) \
    asm volatile("ldmatrix.sync.aligned.m8n8.x4.shared.b16 {%0,%1,%2,%3}, [%4];" \
                 : "=r"(r0), "=r"(r1), "=r"(r2), "=r"(r3) : "r"(addr))
#define LDSM2(r0, r1, addr) \
    asm volatile("ldmatrix.sync.aligned.m8n8.x2.shared.b16 {%0,%1}, [%2];" \
                 : "=r"(r0), "=r"(r1) : "r"(addr))
#define CP16(dst, src) \
    asm volatile("cp.async.cg.shared.global [%0], [%1], 16;" \
                 :: "r"(dst), "l"(src) : "memory")
#define CP_COMMIT() asm volatile("cp.async.commit_group;" ::: "memory")
#define CP_WAIT1()  asm volatile("cp.async.wait_group 1;" ::: "memory")
#define STS128(addr, v) \
    asm volatile("st.shared.v4.b32 [%0], {%1,%2,%3,%4};" \
                 :: "r"(addr), "r"((v).x), "r"((v).y), "r"((v).z), "r"((v).w) : "memory")

__device__ __forceinline__ uint32_t smem_u32(const void* p) {
    uint32_t a;
    asm("{ .reg .u64 t; cvta.to.shared.u64 t, %1; cvt.u32.u64 %0, t; }"
        : "=r"(a) : "l"(p));
    return a;
}

// ======================== graph preprocessing ==============================
__global__ void zero_kernel() {
    int idx = blockIdx.x * blockDim.x + threadIdx.x;
    int stride = gridDim.x * blockDim.x;
    for (int i = idx; i < N_NODES; i += stride) g_cnt[i] = 0;
}

// hist + fused x-convert
__global__ void hist_xconv_kernel(const int* __restrict__ ei, int E,
                                  const float* __restrict__ x) {
    int idx = blockIdx.x * blockDim.x + threadIdx.x;
    int stride = gridDim.x * blockDim.x;
    for (int i = idx; i < N_NODES * 32; i += stride) {
        float4 v = ((const float4*)x)[i];
        uint2 hi, lo;
        split4(v, hi, lo);
        g_xhi[i] = hi;
        g_xlo[i] = lo;
    }
    int E4 = E >> 2;
    const int4* d4 = (const int4*)(ei + E);
    for (int e = idx; e < E4; e += stride) {
        int4 d = d4[e];
        if ((unsigned)d.x < (unsigned)N_NODES) atomicAdd(&g_cnt[d.x], 1);
        if ((unsigned)d.y < (unsigned)N_NODES) atomicAdd(&g_cnt[d.y], 1);
        if ((unsigned)d.z < (unsigned)N_NODES) atomicAdd(&g_cnt[d.z], 1);
        if ((unsigned)d.w < (unsigned)N_NODES) atomicAdd(&g_cnt[d.w], 1);
    }
    for (int e = (E4 << 2) + idx; e < E; e += stride) {
        int d = ei[E + e];
        if ((unsigned)d < (unsigned)N_NODES) atomicAdd(&g_cnt[d], 1);
    }
}

__global__ void scan1_kernel() {
    __shared__ int s[SCAN_BS];
    int tid = threadIdx.x;
    int i = blockIdx.x * SCAN_BS + tid;
    int v = (i < N_NODES) ? g_cnt[i] : 0;
    s[tid] = v;
    __syncthreads();
#pragma unroll
    for (int d = 1; d < SCAN_BS; d <<= 1) {
        int t = (tid >= d) ? s[tid - d] : 0;
        __syncthreads();
        s[tid] += t;
        __syncthreads();
    }
    if (i < N_NODES) g_off[i] = s[tid] - v;
    if (tid == SCAN_BS - 1) g_bsum[blockIdx.x] = s[tid];
}

// scan3 with fused scan2: each block reduces bsum[0..bid) itself
__global__ void scan3_kernel() {
    __shared__ int s[128];
    int bid = blockIdx.x;
    int tid = threadIdx.x;
    if (tid < 128) s[tid] = (tid < bid && tid < SCAN_NB) ? g_bsum[tid] : 0;
    __syncthreads();
#pragma unroll
    for (int d = 64; d > 0; d >>= 1) {
        if (tid < d) s[tid] += s[tid + d];
        __syncthreads();
    }
    int base = s[0];
    int i = bid * SCAN_BS + tid;
    if (i < N_NODES) {
        int off = g_off[i] + base;
        g_off[i] = off;
        g_cur[i] = off;
    }
}

__global__ void fill_kernel(const int* __restrict__ ei, int E) {
    int idx = blockIdx.x * blockDim.x + threadIdx.x;
    int stride = gridDim.x * blockDim.x;
    int E4 = E >> 2;
    const int4* s4 = (const int4*)ei;
    const int4* d4 = (const int4*)(ei + E);
    for (int e = idx; e < E4; e += stride) {
        int4 s = s4[e];
        int4 d = d4[e];
        if ((unsigned)s.x < (unsigned)N_NODES && (unsigned)d.x < (unsigned)N_NODES)
            g_csr[atomicAdd(&g_cur[d.x], 1)] = s.x;
        if ((unsigned)s.y < (unsigned)N_NODES && (unsigned)d.y < (unsigned)N_NODES)
            g_csr[atomicAdd(&g_cur[d.y], 1)] = s.y;
        if ((unsigned)s.z < (unsigned)N_NODES && (unsigned)d.z < (unsigned)N_NODES)
            g_csr[atomicAdd(&g_cur[d.z], 1)] = s.z;
        if ((unsigned)s.w < (unsigned)N_NODES && (unsigned)d.w < (unsigned)N_NODES)
            g_csr[atomicAdd(&g_cur[d.w], 1)] = s.w;
    }
    for (int e = (E4 << 2) + idx; e < E; e += stride) {
        int s = ei[e];
        int d = ei[E + e];
        if ((unsigned)s < (unsigned)N_NODES && (unsigned)d < (unsigned)N_NODES)
            g_csr[atomicAdd(&g_cur[d], 1)] = s;
    }
}

// =============== fused aggregate + HMMA bf16x3 transform ===================
// Persistent 148 CTAs x 256 thr. Per tile (32 rows, all valid):
//  phase G: warp w gathers+means nodes 4w..4w+3 (paired-lane bf16 gather),
//           splits to hi/lo, STS directly into smem A-buffer agg columns.
//           x columns arrive via double-buffered cp.async.
//  phase M: ldmatrix + 3x bf16 MMA + bias epilogue (identical to R11).
__device__ __forceinline__ void prefetch_x(uint32_t sbase, int bufbase,
                                           int tile, int tid) {
    int row0 = tile * TILE_M;
    int a2 = (tid >> 7) & 1;           // 0: xhi, 1: xlo (128 threads each)
    int u = tid & 15;                   // 16B unit within 256B row
    int rbase = (tid >> 4) & 7;         // rows rbase + i*8
    const char* arr = a2 ? (const char*)g_xlo : (const char*)g_xhi;
    uint32_t dbase = sbase + bufbase + 256 + a2 * ABUF_LO + u * 16;
#pragma unroll
    for (int i = 0; i < 4; i++) {
        int r = rbase + i * 8;
        const char* src = arr + (long long)(row0 + r) * 256 + u * 16;
        CP16(dbase + r * LDAB, src);
    }
}

__global__ void __launch_bounds__(256, 1)
fused_kernel(const float* __restrict__ W_l,
             const float* __restrict__ b_l,
             const float* __restrict__ W_r,
             float* __restrict__ out) {
    extern __shared__ char sm[];
    __shared__ float s_bias[128];

    int tid = threadIdx.x;
    int wid = tid >> 5;
    int lane = tid & 31;
    uint32_t sbase = smem_u32(sm);
    if (tid < 128) s_bias[tid] = b_l[tid];

    // B fill once: W -> bf16 hi/lo (rn split)
    for (int idx = tid; idx < 128 * 64; idx += 256) {
        int n = idx >> 6;
        int kq = idx & 63;
        int k = kq * 4;
        const float* src = (k < 128) ? (W_l + n * 128 + k)
                                     : (W_r + n * 128 + (k - 128));
        float4 v = *(const float4*)src;
        uint2 hi, lo;
        split4(v, hi, lo);
        *(uint2*)(sm + OFF_BHI + n * LDAB + kq * 8) = hi;
        *(uint2*)(sm + OFF_BLO + n * LDAB + kq * 8) = lo;
    }

    int wr = (wid & 1) * 16;
    int nb = (wid >> 1) * 32;
    int h = lane >> 4;          // half-warp id
    int hl = lane & 15;

    uint32_t aOff = (wr + (lane & 15)) * LDAB + ((lane >> 4) & 1) * 16;
    uint32_t bHi = sbase + OFF_BHI + (nb + (lane & 7)) * LDAB + ((lane >> 3) & 1) * 16;
    uint32_t bLo = bHi + (OFF_BLO - OFF_BHI);
    const uint4* xh4 = (const uint4*)(const void*)g_xhi;

    int tile = blockIdx.x;
    prefetch_x(sbase, 0, tile, tid);
    CP_COMMIT();

    int it = 0;
    for (; tile < NT2; tile += gridDim.x, it++) {
        int ntile = tile + gridDim.x;
        if (ntile < NT2) prefetch_x(sbase, ((it + 1) & 1) * ABUF_SZ, ntile, tid);
        CP_COMMIT();

        int row0 = tile * TILE_M;
        uint32_t abase = sbase + (it & 1) * ABUF_SZ;

        // ---- phase G: gather + mean 4 nodes per warp, STS into A buffer ----
#pragma unroll
        for (int j = 0; j < 4; j++) {
            int r = wid * 4 + j;
            int node = row0 + r;
            int off = g_off[node];
            int deg = g_cnt[node];
            int end = off + deg;

            float4 accA0 = make_float4(0.f,0.f,0.f,0.f), accA1 = accA0;
            float4 accB0 = accA0, accB1 = accA0;
            int i = off;
            for (; i + 8 <= end; i += 8) {
                int e0 = g_csr[i + h];
                int e1 = g_csr[i + 2 + h];
                int e2 = g_csr[i + 4 + h];
                int e3 = g_csr[i + 6 + h];
                uint4 p0 = xh4[e0 * 16 + hl];
                uint4 p1 = xh4[e1 * 16 + hl];
                uint4 p2 = xh4[e2 * 16 + hl];
                uint4 p3 = xh4[e3 * 16 + hl];
                float4 v;
                v = bf4_to_f4(make_uint2(p0.x, p0.y));
                accA0.x += v.x; accA0.y += v.y; accA0.z += v.z; accA0.w += v.w;
                v = bf4_to_f4(make_uint2(p0.z, p0.w));
                accA1.x += v.x; accA1.y += v.y; accA1.z += v.z; accA1.w += v.w;
                v = bf4_to_f4(make_uint2(p1.x, p1.y));
                accB0.x += v.x; accB0.y += v.y; accB0.z += v.z; accB0.w += v.w;
                v = bf4_to_f4(make_uint2(p1.z, p1.w));
                accB1.x += v.x; accB1.y += v.y; accB1.z += v.z; accB1.w += v.w;
                v = bf4_to_f4(make_uint2(p2.x, p2.y));
                accA0.x += v.x; accA0.y += v.y; accA0.z += v.z; accA0.w += v.w;
                v = bf4_to_f4(make_uint2(p2.z, p2.w));
                accA1.x += v.x; accA1.y += v.y; accA1.z += v.z; accA1.w += v.w;
                v = bf4_to_f4(make_uint2(p3.x, p3.y));
                accB0.x += v.x; accB0.y += v.y; accB0.z += v.z; accB0.w += v.w;
                v = bf4_to_f4(make_uint2(p3.z, p3.w));
                accB1.x += v.x; accB1.y += v.y; accB1.z += v.z; accB1.w += v.w;
            }
            for (; i + 2 <= end; i += 2) {
                int e = g_csr[i + h];
                uint4 p = xh4[e * 16 + hl];
                float4 v = bf4_to_f4(make_uint2(p.x, p.y));
                accA0.x += v.x; accA0.y += v.y; accA0.z += v.z; accA0.w += v.w;
                v = bf4_to_f4(make_uint2(p.z, p.w));
                accA1.x += v.x; accA1.y += v.y; accA1.z += v.z; accA1.w += v.w;
            }
            if (i < end && h == 0) {
                int e = g_csr[i];
                uint4 p = xh4[e * 16 + hl];
                float4 v = bf4_to_f4(make_uint2(p.x, p.y));
                accA0.x += v.x; accA0.y += v.y; accA0.z += v.z; accA0.w += v.w;
                v = bf4_to_f4(make_uint2(p.z, p.w));
                accA1.x += v.x; accA1.y += v.y; accA1.z += v.z; accA1.w += v.w;
            }

            float4 s0, s1;
            s0.x = accA0.x + accB0.x; s0.y = accA0.y + accB0.y;
            s0.z = accA0.z + accB0.z; s0.w = accA0.w + accB0.w;
            s1.x = accA1.x + accB1.x; s1.y = accA1.y + accB1.y;
            s1.z = accA1.z + accB1.z; s1.w = accA1.w + accB1.w;
            s0.x += __shfl_xor_sync(0xFFFFFFFF, s0.x, 16);
            s0.y += __shfl_xor_sync(0xFFFFFFFF, s0.y, 16);
            s0.z += __shfl_xor_sync(0xFFFFFFFF, s0.z, 16);
            s0.w += __shfl_xor_sync(0xFFFFFFFF, s0.w, 16);
            s1.x += __shfl_xor_sync(0xFFFFFFFF, s1.x, 16);
            s1.y += __shfl_xor_sync(0xFFFFFFFF, s1.y, 16);
            s1.z += __shfl_xor_sync(0xFFFFFFFF, s1.z, 16);
            s1.w += __shfl_xor_sync(0xFFFFFFFF, s1.w, 16);

            float sc = 1.f / fmaxf((float)deg, 1.f);
            s0.x *= sc; s0.y *= sc; s0.z *= sc; s0.w *= sc;
            s1.x *= sc; s1.y *= sc; s1.z *= sc; s1.w *= sc;

            if (h == 0) {
                uint2 hi0, lo0, hi1, lo1;
                split4(s0, hi0, lo0);
                split4(s1, hi1, lo1);
                uint32_t rowp = abase + r * LDAB + hl * 16;
                uint4 vh = make_uint4(hi0.x, hi0.y, hi1.x, hi1.y);
                uint4 vl = make_uint4(lo0.x, lo0.y, lo1.x, lo1.y);
                STS128(rowp, vh);
                STS128(rowp + ABUF_LO, vl);
            }
        }

        CP_WAIT1();
        __syncthreads();

        // ---- phase M: MMA + epilogue ----
        int g = lane >> 2;
        int tg = lane & 3;
        int r0 = row0 + wr + g;
        int r1 = r0 + 8;
        int c0 = g_cnt[r0];
        int c1 = g_cnt[r1];

        uint32_t aHi = abase + aOff;
        uint32_t aLo = aHi + ABUF_LO;

        float acc[4][4];
#pragma unroll
        for (int nt = 0; nt < 4; nt++)
#pragma unroll
            for (int jj = 0; jj < 4; jj++) acc[nt][jj] = 0.f;

#pragma unroll 2
        for (int ks = 0; ks < 16; ks++) {
            int kb = ks * 32;
            uint32_t a0, a1, a2, a3, l0, l1, l2, l3;
            LDSM4(a0, a1, a2, a3, aHi + kb);
            LDSM4(l0, l1, l2, l3, aLo + kb);
#pragma unroll
            for (int nt = 0; nt < 4; nt++) {
                uint32_t bh0, bh1, bl0, bl1;
                LDSM2(bh0, bh1, bHi + nt * 8 * LDAB + kb);
                LDSM2(bl0, bl1, bLo + nt * 8 * LDAB + kb);
                MMA16816(acc[nt], a0, a1, a2, a3, bh0, bh1);
                MMA16816(acc[nt], a0, a1, a2, a3, bl0, bl1);
                MMA16816(acc[nt], l0, l1, l2, l3, bh0, bh1);
            }
        }

        float df0 = (c0 > 0) ? 1.f : 0.f;
        float df1 = (c1 > 0) ? 1.f : 0.f;
#pragma unroll
        for (int nt = 0; nt < 4; nt++) {
            int col = nb + nt * 8 + tg * 2;
            float b0 = s_bias[col], b1 = s_bias[col + 1];
            float2 v0 = make_float2(acc[nt][0] + df0 * b0,
                                    acc[nt][1] + df0 * b1);
            *(float2*)(out + (long long)r0 * 128 + col) = v0;
            float2 v1 = make_float2(acc[nt][2] + df1 * b0,
                                    acc[nt][3] + df1 * b1);
            *(float2*)(out + (long long)r1 * 128 + col) = v1;
        }
        __syncthreads();
    }
}

// ---------------------------------------------------------------------------
// Launch
// ---------------------------------------------------------------------------
extern "C" void kernel_launch(void* const* d_in, const int* in_sizes, int n_in,
                              void* d_out, int out_size) {
    const float* x   = (const float*)d_in[0];
    const int*   ei  = (const int*)d_in[1];
    const float* W_l = (const float*)d_in[2];
    const float* b_l = (const float*)d_in[3];
    const float* W_r = (const float*)d_in[4];
    float*       out = (float*)d_out;
    int E = in_sizes[1] / 2;
    if (E > MAXE) E = MAXE;

    cudaFuncSetAttribute(fused_kernel,
                         cudaFuncAttributeMaxDynamicSharedMemorySize, SMEM_T);

    zero_kernel<<<256, 256>>>();
    hist_xconv_kernel<<<2048, 256>>>(ei, E, x);
    scan1_kernel<<<SCAN_NB, SCAN_BS>>>();
    scan3_kernel<<<SCAN_NB, SCAN_BS>>>();
    fill_kernel<<<1024, 256>>>(ei, E);
    fused_kernel<<<148, 256, SMEM_T>>>(W_l, b_l, W_r, out);
}

// round 13
// speedup vs baseline: 1.6877x; 1.6877x over previous
#include <cuda_runtime.h>
#include <cuda_bf16.h>
#include <cstdint>

#define N_NODES 100000
#define F 128
#define MAXE 1600000
#define SCAN_BS 1024
#define SCAN_NB ((N_NODES + SCAN_BS - 1) / SCAN_BS)   // 98

#define TILE_M 32
#define NT2 (N_NODES / TILE_M)                         // 3125 exact
#define LDAB 528                                       // 512B data + 16B pad
#define ABUF_LO 16896
#define ABUF_SZ 33792
#define OFF_BHI (2 * ABUF_SZ)                          // 67584
#define OFF_BLO (OFF_BHI + 128 * LDAB)                 // 135168
#define SMEM_T  (OFF_BLO + 128 * LDAB)                 // 202752

// Scratch (allocation-free rule: __device__ globals)
__device__ int   g_cnt[N_NODES];
__device__ int   g_cur[N_NODES];
__device__ int   g_off[N_NODES];
__device__ int   g_bsum[SCAN_NB + 1];
__device__ int   g_csr[MAXE];
// bf16 hi/lo packed: one uint2 = 4 bf16 (8B); 128 feats = 32 uint2 = 256B/row
__device__ uint2 g_agghi[N_NODES * 32];
__device__ uint2 g_agglo[N_NODES * 32];
__device__ uint2 g_xhi[N_NODES * 32];
__device__ uint2 g_xlo[N_NODES * 32];

// ---- bf16 rn split: hi = rn(v) (unbiased), lo = rn(v - float(hi)) ----
__device__ __forceinline__ uint32_t cvt2(float f0, float f1) {
    uint32_t d;
    asm("cvt.rn.bf16x2.f32 %0, %1, %2;" : "=r"(d) : "f"(f1), "f"(f0));
    return d;
}
__device__ __forceinline__ float4 bf4_to_f4(uint2 p) {
    float2 a = __bfloat1622float2(*(const __nv_bfloat162*)&p.x);
    float2 b = __bfloat1622float2(*(const __nv_bfloat162*)&p.y);
    return make_float4(a.x, a.y, b.x, b.y);
}
__device__ __forceinline__ void split4(float4 v, uint2& hi, uint2& lo) {
    hi.x = cvt2(v.x, v.y);
    hi.y = cvt2(v.z, v.w);
    float4 h = bf4_to_f4(hi);
    lo.x = cvt2(v.x - h.x, v.y - h.y);
    lo.y = cvt2(v.z - h.z, v.w - h.w);
}

#define MMA16816(c, a0, a1, a2, a3, b0, b1) \
    asm volatile("mma.sync.aligned.m16n8k16.row.col.f32.bf16.bf16.f32 " \
                 "{%0,%1,%2,%3}, {%4,%5,%6,%7}, {%8,%9}, {%0,%1,%2,%3};" \
                 : "+f"((c)[0]), "+f"((c)[1]), "+f"((c)[2]), "+f"((c)[3]) \
                 : "r"(a0), "r"(a1), "r"(a2), "r"(a3), "r"(b0), "r"(b1))
#define LDSM4(r0, r1, r2, r3, addr) \
    asm volatile("ldmatrix.sync.aligned.m8n8.x4.shared.b16 {%0,%1,%2,%3}, [%4];" \
                 : "=r"(r0), "=r"(r1), "=r"(r2), "=r"(r3) : "r"(addr))
#define LDSM2(r0, r1, addr) \
    asm volatile("ldmatrix.sync.aligned.m8n8.x2.shared.b16 {%0,%1}, [%2];" \
                 : "=r"(r0), "=r"(r1) : "r"(addr))
#define CP16(dst, src, ssz) \
    asm volatile("cp.async.cg.shared.global [%0], [%1], 16, %2;" \
                 :: "r"(dst), "l"(src), "r"(ssz) : "memory")
#define CP_COMMIT() asm volatile("cp.async.commit_group;" ::: "memory")
#define CP_WAIT1()  asm volatile("cp.async.wait_group 1;" ::: "memory")

__device__ __forceinline__ uint32_t smem_u32(const void* p) {
    uint32_t a;
    asm("{ .reg .u64 t; cvta.to.shared.u64 t, %1; cvt.u32.u64 %0, t; }"
        : "=r"(a) : "l"(p));
    return a;
}

// ======================== graph preprocessing ==============================
__global__ void zero_kernel() {
    int idx = blockIdx.x * blockDim.x + threadIdx.x;
    int stride = gridDim.x * blockDim.x;
    for (int i = idx; i < N_NODES; i += stride) g_cnt[i] = 0;
}

// hist + fused x-convert (uint4 stores)
__global__ void hist_xconv_kernel(const int* __restrict__ ei, int E,
                                  const float* __restrict__ x) {
    int idx = blockIdx.x * blockDim.x + threadIdx.x;
    int stride = gridDim.x * blockDim.x;
    // xconv: process 8 floats per iter, one uint4 store per array
    uint4* xhi4 = (uint4*)(void*)g_xhi;
    uint4* xlo4 = (uint4*)(void*)g_xlo;
    for (int i = idx; i < N_NODES * 16; i += stride) {
        float4 v0 = ((const float4*)x)[i * 2];
        float4 v1 = ((const float4*)x)[i * 2 + 1];
        uint2 h0, l0, h1, l1;
        split4(v0, h0, l0);
        split4(v1, h1, l1);
        xhi4[i] = make_uint4(h0.x, h0.y, h1.x, h1.y);
        xlo4[i] = make_uint4(l0.x, l0.y, l1.x, l1.y);
    }
    // hist
    int E4 = E >> 2;
    const int4* d4 = (const int4*)(ei + E);
    for (int e = idx; e < E4; e += stride) {
        int4 d = d4[e];
        if ((unsigned)d.x < (unsigned)N_NODES) atomicAdd(&g_cnt[d.x], 1);
        if ((unsigned)d.y < (unsigned)N_NODES) atomicAdd(&g_cnt[d.y], 1);
        if ((unsigned)d.z < (unsigned)N_NODES) atomicAdd(&g_cnt[d.z], 1);
        if ((unsigned)d.w < (unsigned)N_NODES) atomicAdd(&g_cnt[d.w], 1);
    }
    for (int e = (E4 << 2) + idx; e < E; e += stride) {
        int d = ei[E + e];
        if ((unsigned)d < (unsigned)N_NODES) atomicAdd(&g_cnt[d], 1);
    }
}

__global__ void scan1_kernel() {
    __shared__ int s[SCAN_BS];
    int tid = threadIdx.x;
    int i = blockIdx.x * SCAN_BS + tid;
    int v = (i < N_NODES) ? g_cnt[i] : 0;
    s[tid] = v;
    __syncthreads();
#pragma unroll
    for (int d = 1; d < SCAN_BS; d <<= 1) {
        int t = (tid >= d) ? s[tid - d] : 0;
        __syncthreads();
        s[tid] += t;
        __syncthreads();
    }
    if (i < N_NODES) g_off[i] = s[tid] - v;
    if (tid == SCAN_BS - 1) g_bsum[blockIdx.x] = s[tid];
}

// scan3 with fused scan2: each block reduces bsum[0..bid) itself
__global__ void scan3_kernel() {
    __shared__ int s[128];
    int bid = blockIdx.x;
    int tid = threadIdx.x;
    if (tid < 128) s[tid] = (tid < bid && tid < SCAN_NB) ? g_bsum[tid] : 0;
    __syncthreads();
#pragma unroll
    for (int d = 64; d > 0; d >>= 1) {
        if (tid < d) s[tid] += s[tid + d];
        __syncthreads();
    }
    int base = s[0];
    int i = bid * SCAN_BS + tid;
    if (i < N_NODES) {
        int off = g_off[i] + base;
        g_off[i] = off;
        g_cur[i] = off;
    }
}

__global__ void fill_kernel(const int* __restrict__ ei, int E) {
    int idx = blockIdx.x * blockDim.x + threadIdx.x;
    int stride = gridDim.x * blockDim.x;
    int E4 = E >> 2;
    const int4* s4 = (const int4*)ei;
    const int4* d4 = (const int4*)(ei + E);
    for (int e = idx; e < E4; e += stride) {
        int4 s = s4[e];
        int4 d = d4[e];
        if ((unsigned)s.x < (unsigned)N_NODES && (unsigned)d.x < (unsigned)N_NODES)
            g_csr[atomicAdd(&g_cur[d.x], 1)] = s.x;
        if ((unsigned)s.y < (unsigned)N_NODES && (unsigned)d.y < (unsigned)N_NODES)
            g_csr[atomicAdd(&g_cur[d.y], 1)] = s.y;
        if ((unsigned)s.z < (unsigned)N_NODES && (unsigned)d.z < (unsigned)N_NODES)
            g_csr[atomicAdd(&g_cur[d.z], 1)] = s.z;
        if ((unsigned)s.w < (unsigned)N_NODES && (unsigned)d.w < (unsigned)N_NODES)
            g_csr[atomicAdd(&g_cur[d.w], 1)] = s.w;
    }
    for (int e = (E4 << 2) + idx; e < E; e += stride) {
        int s = ei[e];
        int d = ei[E + e];
        if ((unsigned)s < (unsigned)N_NODES && (unsigned)d < (unsigned)N_NODES)
            g_csr[atomicAdd(&g_cur[d], 1)] = s;
    }
}

// ---- aggregate: warp per node; paired-lane bf16 gather (LDG.128) ----
__global__ void aggregate_kernel() {
    int gtid = blockIdx.x * blockDim.x + threadIdx.x;
    int w = gtid >> 5;
    int lane = gtid & 31;
    if (w >= N_NODES) return;
    int off = g_off[w];
    int deg = g_cnt[w];
    int end = off + deg;

    int h = lane >> 4;         // half-warp id
    int hl = lane & 15;        // 16B unit within 256B row
    const uint4* xh4 = (const uint4*)(const void*)g_xhi;

    float4 accA0 = make_float4(0.f,0.f,0.f,0.f), accA1 = accA0;
    float4 accB0 = accA0, accB1 = accA0;

    int i = off;
    for (; i + 8 <= end; i += 8) {
        int e0 = g_csr[i + h];
        int e1 = g_csr[i + 2 + h];
        int e2 = g_csr[i + 4 + h];
        int e3 = g_csr[i + 6 + h];
        uint4 p0 = xh4[e0 * 16 + hl];
        uint4 p1 = xh4[e1 * 16 + hl];
        uint4 p2 = xh4[e2 * 16 + hl];
        uint4 p3 = xh4[e3 * 16 + hl];
        float4 v;
        v = bf4_to_f4(make_uint2(p0.x, p0.y));
        accA0.x += v.x; accA0.y += v.y; accA0.z += v.z; accA0.w += v.w;
        v = bf4_to_f4(make_uint2(p0.z, p0.w));
        accA1.x += v.x; accA1.y += v.y; accA1.z += v.z; accA1.w += v.w;
        v = bf4_to_f4(make_uint2(p1.x, p1.y));
        accB0.x += v.x; accB0.y += v.y; accB0.z += v.z; accB0.w += v.w;
        v = bf4_to_f4(make_uint2(p1.z, p1.w));
        accB1.x += v.x; accB1.y += v.y; accB1.z += v.z; accB1.w += v.w;
        v = bf4_to_f4(make_uint2(p2.x, p2.y));
        accA0.x += v.x; accA0.y += v.y; accA0.z += v.z; accA0.w += v.w;
        v = bf4_to_f4(make_uint2(p2.z, p2.w));
        accA1.x += v.x; accA1.y += v.y; accA1.z += v.z; accA1.w += v.w;
        v = bf4_to_f4(make_uint2(p3.x, p3.y));
        accB0.x += v.x; accB0.y += v.y; accB0.z += v.z; accB0.w += v.w;
        v = bf4_to_f4(make_uint2(p3.z, p3.w));
        accB1.x += v.x; accB1.y += v.y; accB1.z += v.z; accB1.w += v.w;
    }
    for (; i + 2 <= end; i += 2) {
        int e = g_csr[i + h];
        uint4 p = xh4[e * 16 + hl];
        float4 v = bf4_to_f4(make_uint2(p.x, p.y));
        accA0.x += v.x; accA0.y += v.y; accA0.z += v.z; accA0.w += v.w;
        v = bf4_to_f4(make_uint2(p.z, p.w));
        accA1.x += v.x; accA1.y += v.y; accA1.z += v.z; accA1.w += v.w;
    }
    if (i < end && h == 0) {
        int e = g_csr[i];
        uint4 p = xh4[e * 16 + hl];
        float4 v = bf4_to_f4(make_uint2(p.x, p.y));
        accA0.x += v.x; accA0.y += v.y; accA0.z += v.z; accA0.w += v.w;
        v = bf4_to_f4(make_uint2(p.z, p.w));
        accA1.x += v.x; accA1.y += v.y; accA1.z += v.z; accA1.w += v.w;
    }

    float4 s0, s1;
    s0.x = accA0.x + accB0.x; s0.y = accA0.y + accB0.y;
    s0.z = accA0.z + accB0.z; s0.w = accA0.w + accB0.w;
    s1.x = accA1.x + accB1.x; s1.y = accA1.y + accB1.y;
    s1.z = accA1.z + accB1.z; s1.w = accA1.w + accB1.w;
    s0.x += __shfl_xor_sync(0xFFFFFFFF, s0.x, 16);
    s0.y += __shfl_xor_sync(0xFFFFFFFF, s0.y, 16);
    s0.z += __shfl_xor_sync(0xFFFFFFFF, s0.z, 16);
    s0.w += __shfl_xor_sync(0xFFFFFFFF, s0.w, 16);
    s1.x += __shfl_xor_sync(0xFFFFFFFF, s1.x, 16);
    s1.y += __shfl_xor_sync(0xFFFFFFFF, s1.y, 16);
    s1.z += __shfl_xor_sync(0xFFFFFFFF, s1.z, 16);
    s1.w += __shfl_xor_sync(0xFFFFFFFF, s1.w, 16);

    float sc = 1.f / fmaxf((float)deg, 1.f);
    s0.x *= sc; s0.y *= sc; s0.z *= sc; s0.w *= sc;
    s1.x *= sc; s1.y *= sc; s1.z *= sc; s1.w *= sc;

    // half 0 writes BOTH quads once, as uint4 (fix: was double-written before)
    if (h == 0) {
        uint2 hi0, lo0, hi1, lo1;
        split4(s0, hi0, lo0);
        split4(s1, hi1, lo1);
        ((uint4*)(void*)g_agghi)[w * 16 + hl] = make_uint4(hi0.x, hi0.y, hi1.x, hi1.y);
        ((uint4*)(void*)g_agglo)[w * 16 + hl] = make_uint4(lo0.x, lo0.y, lo1.x, lo1.y);
    }
}

// ===================== HMMA bf16x3 transform (pipelined) ===================
__device__ __forceinline__ void prefetch_A(uint32_t sbase, int bufbase,
                                           int tile, int tid) {
    int row0 = tile * TILE_M;
    int op = tid & 63;
    int a2 = op >> 4;          // 0 agghi, 1 xhi, 2 agglo, 3 xlo
    int u = op & 15;
    const char* arr;
    if (a2 == 0)      arr = (const char*)g_agghi;
    else if (a2 == 1) arr = (const char*)g_xhi;
    else if (a2 == 2) arr = (const char*)g_agglo;
    else              arr = (const char*)g_xlo;
    uint32_t dbase = sbase + bufbase + (a2 & 1) * 256 + (a2 >> 1) * ABUF_LO + u * 16;
    int rbase = tid >> 6;      // 0..3
#pragma unroll
    for (int i = 0; i < 8; i++) {
        int r = rbase + i * 4;
        int row = row0 + r;
        int ok = (row < N_NODES) ? 16 : 0;
        const char* src = arr + (long long)min(row, N_NODES - 1) * 256 + u * 16;
        CP16(dbase + r * LDAB, src, ok);
    }
}

__global__ void __launch_bounds__(256, 1)
transform_hmma(const float* __restrict__ W_l,
               const float* __restrict__ b_l,
               const float* __restrict__ W_r,
               float* __restrict__ out) {
    extern __shared__ char sm[];
    __shared__ float s_bias[128];

    int tid = threadIdx.x;
    int wid = tid >> 5;
    int lane = tid & 31;
    uint32_t sbase = smem_u32(sm);
    if (tid < 128) s_bias[tid] = b_l[tid];

    // B fill once: W -> bf16 hi/lo (rn split)
    for (int idx = tid; idx < 128 * 64; idx += 256) {
        int n = idx >> 6;
        int kq = idx & 63;
        int k = kq * 4;
        const float* src = (k < 128) ? (W_l + n * 128 + k)
                                     : (W_r + n * 128 + (k - 128));
        float4 v = *(const float4*)src;
        uint2 hi, lo;
        split4(v, hi, lo);
        *(uint2*)(sm + OFF_BHI + n * LDAB + kq * 8) = hi;
        *(uint2*)(sm + OFF_BLO + n * LDAB + kq * 8) = lo;
    }

    int wr = (wid & 1) * 16;
    int nb = (wid >> 1) * 32;

    uint32_t aOff = (wr + (lane & 15)) * LDAB + ((lane >> 4) & 1) * 16;
    uint32_t bHi = sbase + OFF_BHI + (nb + (lane & 7)) * LDAB + ((lane >> 3) & 1) * 16;
    uint32_t bLo = bHi + (OFF_BLO - OFF_BHI);

    int tile = blockIdx.x;
    prefetch_A(sbase, 0, tile, tid);
    CP_COMMIT();

    int it = 0;
    for (; tile < NT2; tile += gridDim.x, it++) {
        int ntile = tile + gridDim.x;
        if (ntile < NT2) prefetch_A(sbase, ((it + 1) & 1) * ABUF_SZ, ntile, tid);
        CP_COMMIT();
        CP_WAIT1();
        __syncthreads();

        int row0 = tile * TILE_M;
        int g = lane >> 2;
        int tg = lane & 3;
        int r0 = row0 + wr + g;
        int r1 = r0 + 8;
        int c0 = g_cnt[r0];
        int c1 = g_cnt[r1];

        uint32_t abase = sbase + (it & 1) * ABUF_SZ;
        uint32_t aHi = abase + aOff;
        uint32_t aLo = aHi + ABUF_LO;

        float acc[4][4];
#pragma unroll
        for (int nt = 0; nt < 4; nt++)
#pragma unroll
            for (int j = 0; j < 4; j++) acc[nt][j] = 0.f;

#pragma unroll 2
        for (int ks = 0; ks < 16; ks++) {
            int kb = ks * 32;
            uint32_t a0, a1, a2, a3, l0, l1, l2, l3;
            LDSM4(a0, a1, a2, a3, aHi + kb);
            LDSM4(l0, l1, l2, l3, aLo + kb);
#pragma unroll
            for (int nt = 0; nt < 4; nt++) {
                uint32_t bh0, bh1, bl0, bl1;
                LDSM2(bh0, bh1, bHi + nt * 8 * LDAB + kb);
                LDSM2(bl0, bl1, bLo + nt * 8 * LDAB + kb);
                MMA16816(acc[nt], a0, a1, a2, a3, bh0, bh1);
                MMA16816(acc[nt], a0, a1, a2, a3, bl0, bl1);
                MMA16816(acc[nt], l0, l1, l2, l3, bh0, bh1);
            }
        }

        float df0 = (c0 > 0) ? 1.f : 0.f;
        float df1 = (c1 > 0) ? 1.f : 0.f;
#pragma unroll
        for (int nt = 0; nt < 4; nt++) {
            int col = nb + nt * 8 + tg * 2;
            float b0 = s_bias[col], b1 = s_bias[col + 1];
            float2 v0 = make_float2(acc[nt][0] + df0 * b0,
                                    acc[nt][1] + df0 * b1);
            *(float2*)(out + (long long)r0 * 128 + col) = v0;
            float2 v1 = make_float2(acc[nt][2] + df1 * b0,
                                    acc[nt][3] + df1 * b1);
            *(float2*)(out + (long long)r1 * 128 + col) = v1;
        }
        __syncthreads();
    }
}

// ---------------------------------------------------------------------------
// Launch
// ---------------------------------------------------------------------------
extern "C" void kernel_launch(void* const* d_in, const int* in_sizes, int n_in,
                              void* d_out, int out_size) {
    const float* x   = (const float*)d_in[0];
    const int*   ei  = (const int*)d_in[1];
    const float* W_l = (const float*)d_in[2];
    const float* b_l = (const float*)d_in[3];
    const float* W_r = (const float*)d_in[4];
    float*       out = (float*)d_out;
    int E = in_sizes[1] / 2;
    if (E > MAXE) E = MAXE;

    cudaFuncSetAttribute(transform_hmma,
                         cudaFuncAttributeMaxDynamicSharedMemorySize, SMEM_T);

    zero_kernel<<<256, 256>>>();
    hist_xconv_kernel<<<2048, 256>>>(ei, E, x);
    scan1_kernel<<<SCAN_NB, SCAN_BS>>>();
    scan3_kernel<<<SCAN_NB, SCAN_BS>>>();
    fill_kernel<<<1024, 256>>>(ei, E);
    aggregate_kernel<<<(N_NODES * 32 + 255) / 256, 256>>>();
    transform_hmma<<<148, 256, SMEM_T>>>(W_l, b_l, W_r, out);
}